// round 3
// baseline (speedup 1.0000x reference)
#include <cuda_runtime.h>

#define N_NODES 100000
#define F 128
#define BN_EPS 1e-5f

// Scratch (allocation-free rule: __device__ globals)
__device__ float g_a[(size_t)N_NODES * F];   // t1 = x@W1, later h2 = relu(bn(h1))@W2
__device__ float g_b[(size_t)N_NODES * F];   // h1 = spmm(t1) + b1
__device__ float g_stats[2 * F];             // [sum per feature, sumsq per feature]

// ---------------------------------------------------------------------------
// Init: h1 <- b1 broadcast, out <- b2 broadcast, stats <- 0
// ---------------------------------------------------------------------------
__global__ void init_kernel(float* __restrict__ h1, float* __restrict__ out,
                            const float* __restrict__ b1, const float* __restrict__ b2) {
    int idx = blockIdx.x * blockDim.x + threadIdx.x;
    if (idx < 2 * F) g_stats[idx] = 0.0f;
    const float4* b14 = (const float4*)b1;
    const float4* b24 = (const float4*)b2;
    float4* h14 = (float4*)h1;
    float4* out4 = (float4*)out;
    const int total = N_NODES * (F / 4);
    const int stride = gridDim.x * blockDim.x;
    for (int i = idx; i < total; i += stride) {
        int c4 = i & (F / 4 - 1);
        h14[i] = b14[c4];
        out4[i] = b24[c4];
    }
}

// ---------------------------------------------------------------------------
// GEMM: out[r, :] = (transform(X[r, :])) @ W,   W is [128,128] row-major.
// Block: 256 threads, 64 rows per block. X tile in smem; W streamed via L1
// (64KB, fully cache-resident, every block reads the same rows -> broadcast).
// FUSE_BN applies y = relu(gamma*(x-mean)*rsqrt(var+eps)+beta) on tile load.
// ---------------------------------------------------------------------------
template <bool FUSE_BN>
__global__ void gemm128_kernel(const float* __restrict__ X, const float* __restrict__ W,
                               float* __restrict__ out, int nrows,
                               const float* __restrict__ gamma,
                               const float* __restrict__ beta) {
    __shared__ float xs[64 * F];
    __shared__ float scale_s[F];
    __shared__ float shift_s[F];

    const int tid = threadIdx.x;

    if (FUSE_BN) {
        if (tid < F) {
            const float inv = 1.0f / (float)N_NODES;
            float mean = g_stats[tid] * inv;
            float var = g_stats[F + tid] * inv - mean * mean;
            float sc = gamma[tid] * rsqrtf(var + BN_EPS);
            scale_s[tid] = sc;
            shift_s[tid] = beta[tid] - mean * sc;
        }
        __syncthreads();
    }

    const int row0 = blockIdx.x * 64;
    const float4* X4 = (const float4*)X;
    float4* xs4 = (float4*)xs;

    // Load 64x128 X tile (float4-vectorized), applying BN+ReLU if fused.
    for (int i = tid; i < 64 * (F / 4); i += 256) {
        int r = i >> 5;          // local row
        int c4 = i & 31;         // float4 column
        int gr = row0 + r;
        float4 v = make_float4(0.f, 0.f, 0.f, 0.f);
        if (gr < nrows) v = X4[(size_t)gr * (F / 4) + c4];
        if (FUSE_BN) {
            int f = c4 * 4;
            v.x = fmaxf(fmaf(v.x, scale_s[f + 0], shift_s[f + 0]), 0.f);
            v.y = fmaxf(fmaf(v.y, scale_s[f + 1], shift_s[f + 1]), 0.f);
            v.z = fmaxf(fmaf(v.z, scale_s[f + 2], shift_s[f + 2]), 0.f);
            v.w = fmaxf(fmaf(v.w, scale_s[f + 3], shift_s[f + 3]), 0.f);
        }
        xs4[i] = v;
    }
    __syncthreads();

    const int warp = tid >> 5;
    const int lane = tid & 31;
    const int rbase = warp * 8;  // 8 rows per warp, 4 cols per lane

    float4 acc[8];
#pragma unroll
    for (int i = 0; i < 8; i++) acc[i] = make_float4(0.f, 0.f, 0.f, 0.f);

    const float4* W4 = (const float4*)W;
#pragma unroll 4
    for (int k = 0; k < F; k++) {
        float4 wv = W4[k * 32 + lane];   // full 512B row per warp, L1-cached
#pragma unroll
        for (int i = 0; i < 8; i++) {
            float xv = xs[(rbase + i) * F + k];   // smem broadcast within warp
            acc[i].x = fmaf(xv, wv.x, acc[i].x);
            acc[i].y = fmaf(xv, wv.y, acc[i].y);
            acc[i].z = fmaf(xv, wv.z, acc[i].z);
            acc[i].w = fmaf(xv, wv.w, acc[i].w);
        }
    }

#pragma unroll
    for (int i = 0; i < 8; i++) {
        int gr = row0 + rbase + i;
        if (gr < nrows)
            *(float4*)&out[(size_t)gr * F + lane * 4] = acc[i];
    }
}

// ---------------------------------------------------------------------------
// SpMM (COO): dst[row, :] += w * src[col, :] via warp-per-edge.
// Each lane handles 4 contiguous floats (float4 gather + red.global.add.v4).
// Edge metadata loaded 32-at-a-time, broadcast with shfl.
// ---------------------------------------------------------------------------
__global__ void spmm_kernel(const int* __restrict__ rows, const int* __restrict__ cols,
                            const float* __restrict__ ew,
                            const float* __restrict__ src, float* __restrict__ dst,
                            int E) {
    const int lane = threadIdx.x & 31;
    const int warp = (blockIdx.x * blockDim.x + threadIdx.x) >> 5;
    const int nwarps = (gridDim.x * blockDim.x) >> 5;

    for (int base = warp * 32; base < E; base += nwarps * 32) {
        int n = min(32, E - base);
        int r = 0, c = 0;
        float w = 0.f;
        if (lane < n) {
            r = rows[base + lane];
            c = cols[base + lane];
            w = ew[base + lane];
        }
        for (int j = 0; j < n; j++) {
            int rj = __shfl_sync(0xffffffffu, r, j);
            int cj = __shfl_sync(0xffffffffu, c, j);
            float wj = __shfl_sync(0xffffffffu, w, j);
            float4 v = *(const float4*)(src + (size_t)cj * F + lane * 4);
            float* p = dst + (size_t)rj * F + lane * 4;
            asm volatile("red.global.add.v4.f32 [%0], {%1, %2, %3, %4};"
                         :: "l"(p), "f"(v.x * wj), "f"(v.y * wj),
                            "f"(v.z * wj), "f"(v.w * wj)
                         : "memory");
        }
    }
}

// ---------------------------------------------------------------------------
// BN stats: per-feature sum and sum-of-squares over all nodes.
// ---------------------------------------------------------------------------
__global__ void bn_stats_kernel(const float* __restrict__ h) {
    const int f = threadIdx.x & (F - 1);
    const int half = threadIdx.x >> 7;  // 0 or 1
    float s = 0.f, s2 = 0.f;
    for (int r = blockIdx.x * 2 + half; r < N_NODES; r += gridDim.x * 2) {
        float v = h[(size_t)r * F + f];
        s += v;
        s2 += v * v;
    }
    __shared__ float sh[256];
    __shared__ float sh2[256];
    sh[threadIdx.x] = s;
    sh2[threadIdx.x] = s2;
    __syncthreads();
    if (half == 0) {
        atomicAdd(&g_stats[f], s + sh[threadIdx.x + 128]);
        atomicAdd(&g_stats[F + f], s2 + sh2[threadIdx.x + 128]);
    }
}

// ---------------------------------------------------------------------------
// Launch: init -> gemm1 -> spmm1 -> stats -> gemm2(fused BN/ReLU) -> spmm2
// ---------------------------------------------------------------------------
extern "C" void kernel_launch(void* const* d_in, const int* in_sizes, int n_in,
                              void* d_out, int out_size) {
    const float* x     = (const float*)d_in[0];
    const int*   erow  = (const int*)d_in[1];
    const int*   ecol  = (const int*)d_in[2];
    const float* ew    = (const float*)d_in[3];
    const float* W1    = (const float*)d_in[4];
    const float* b1    = (const float*)d_in[5];
    const float* W2    = (const float*)d_in[6];
    const float* b2    = (const float*)d_in[7];
    const float* gamma = (const float*)d_in[8];
    const float* beta  = (const float*)d_in[9];
    float* out = (float*)d_out;
    const int E = in_sizes[1];

    float *ga, *gb;
    cudaGetSymbolAddress((void**)&ga, g_a);
    cudaGetSymbolAddress((void**)&gb, g_b);

    const int gemm_blocks = (N_NODES + 63) / 64;

    // h1 <- b1, out <- b2, stats <- 0
    init_kernel<<<2048, 256>>>(gb, out, b1, b2);
    // t1 = x @ W1
    gemm128_kernel<false><<<gemm_blocks, 256>>>(x, W1, ga, N_NODES, nullptr, nullptr);
    // h1 += A @ t1
    spmm_kernel<<<4096, 256>>>(erow, ecol, ew, ga, gb, E);
    // per-feature stats of h1
    bn_stats_kernel<<<1024, 256>>>(gb);
    // h2 = relu(bn(h1)) @ W2
    gemm128_kernel<true><<<gemm_blocks, 256>>>(gb, W2, ga, N_NODES, gamma, beta);
    // out += A @ h2
    spmm_kernel<<<4096, 256>>>(erow, ecol, ew, ga, out, E);
}

// round 4
// speedup vs baseline: 1.3175x; 1.3175x over previous
#include <cuda_runtime.h>

#define N_NODES 100000
#define N_EDGES_MAX 1600000
#define F 128
#define BN_EPS 1e-5f
#define CHUNK 1024
#define NCHUNKS ((N_NODES + CHUNK - 1) / CHUNK)   // 98

// Scratch (allocation-free rule: __device__ globals)
__device__ float g_a[(size_t)N_NODES * F];     // t1 = x@W1, later h2
__device__ float g_b[(size_t)N_NODES * F];     // h1
__device__ float g_stats[2 * F];               // [sum, sumsq] per feature
__device__ int   g_count[N_NODES];
__device__ int   g_row_start[N_NODES + 1];
__device__ int   g_cursor[N_NODES];
__device__ int   g_chunksum[NCHUNKS];
__device__ int   g_chunkoff[NCHUNKS];
__device__ int2  g_ecw[N_EDGES_MAX];           // packed {col, weight-bits} per edge, row-grouped

// ---------------------------------------------------------------------------
// CSR build step 0: zero counts + stats
// ---------------------------------------------------------------------------
__global__ void zero_kernel() {
    int idx = blockIdx.x * blockDim.x + threadIdx.x;
    if (idx < 2 * F) g_stats[idx] = 0.0f;
    for (int i = idx; i < N_NODES; i += gridDim.x * blockDim.x)
        g_count[i] = 0;
}

// Step 1: per-row degree histogram
__global__ void hist_kernel(const int* __restrict__ rows, int E) {
    int idx = blockIdx.x * blockDim.x + threadIdx.x;
    for (int e = idx; e < E; e += gridDim.x * blockDim.x)
        atomicAdd(&g_count[rows[e]], 1);
}

// Step 2a: per-chunk exclusive scan (Hillis-Steele, 1024 threads = 1 chunk)
__global__ void scan1_kernel() {
    __shared__ int sm[CHUNK];
    int tid = threadIdx.x;
    int i = blockIdx.x * CHUNK + tid;
    int val = (i < N_NODES) ? g_count[i] : 0;
    sm[tid] = val;
    __syncthreads();
    for (int off = 1; off < CHUNK; off <<= 1) {
        int t = (tid >= off) ? sm[tid - off] : 0;
        __syncthreads();
        sm[tid] += t;
        __syncthreads();
    }
    if (i < N_NODES) g_row_start[i] = sm[tid] - val;   // exclusive within chunk
    if (tid == CHUNK - 1) g_chunksum[blockIdx.x] = sm[tid];
}

// Step 2b: scan chunk totals (single block)
__global__ void scan2_kernel() {
    __shared__ int sm[128];
    int tid = threadIdx.x;
    int val = (tid < NCHUNKS) ? g_chunksum[tid] : 0;
    sm[tid] = val;
    __syncthreads();
    for (int off = 1; off < 128; off <<= 1) {
        int t = (tid >= off) ? sm[tid - off] : 0;
        __syncthreads();
        sm[tid] += t;
        __syncthreads();
    }
    if (tid < NCHUNKS) g_chunkoff[tid] = sm[tid] - val;
}

// Step 2c: add chunk offsets, init cursors, cap row_start
__global__ void scan3_kernel(int E) {
    int i = blockIdx.x * blockDim.x + threadIdx.x;
    if (i < N_NODES) {
        int rs = g_row_start[i] + g_chunkoff[i / CHUNK];
        g_row_start[i] = rs;
        g_cursor[i] = rs;
    } else if (i == N_NODES) {
        g_row_start[N_NODES] = E;
    }
}

// Step 3: scatter edges into row-grouped order (col + weight packed, 8B each)
__global__ void scatter_kernel(const int* __restrict__ rows, const int* __restrict__ cols,
                               const float* __restrict__ ew, int E) {
    int idx = blockIdx.x * blockDim.x + threadIdx.x;
    for (int e = idx; e < E; e += gridDim.x * blockDim.x) {
        int pos = atomicAdd(&g_cursor[rows[e]], 1);
        g_ecw[pos] = make_int2(cols[e], __float_as_int(ew[e]));
    }
}

// ---------------------------------------------------------------------------
// GEMM: out[r,:] = transform(X[r,:]) @ W, W [128,128] row-major.
// 256 threads / 64 rows per block; W rows L1-broadcast; optional fused BN+ReLU.
// ---------------------------------------------------------------------------
template <bool FUSE_BN>
__global__ void gemm128_kernel(const float* __restrict__ X, const float* __restrict__ W,
                               float* __restrict__ out, int nrows,
                               const float* __restrict__ gamma,
                               const float* __restrict__ beta) {
    __shared__ float xs[64 * F];
    __shared__ float scale_s[F];
    __shared__ float shift_s[F];

    const int tid = threadIdx.x;

    if (FUSE_BN) {
        if (tid < F) {
            const float inv = 1.0f / (float)N_NODES;
            float mean = g_stats[tid] * inv;
            float var = g_stats[F + tid] * inv - mean * mean;
            float sc = gamma[tid] * rsqrtf(var + BN_EPS);
            scale_s[tid] = sc;
            shift_s[tid] = beta[tid] - mean * sc;
        }
        __syncthreads();
    }

    const int row0 = blockIdx.x * 64;
    const float4* X4 = (const float4*)X;
    float4* xs4 = (float4*)xs;

    for (int i = tid; i < 64 * (F / 4); i += 256) {
        int r = i >> 5;
        int c4 = i & 31;
        int gr = row0 + r;
        float4 v = make_float4(0.f, 0.f, 0.f, 0.f);
        if (gr < nrows) v = X4[(size_t)gr * (F / 4) + c4];
        if (FUSE_BN) {
            int f = c4 * 4;
            v.x = fmaxf(fmaf(v.x, scale_s[f + 0], shift_s[f + 0]), 0.f);
            v.y = fmaxf(fmaf(v.y, scale_s[f + 1], shift_s[f + 1]), 0.f);
            v.z = fmaxf(fmaf(v.z, scale_s[f + 2], shift_s[f + 2]), 0.f);
            v.w = fmaxf(fmaf(v.w, scale_s[f + 3], shift_s[f + 3]), 0.f);
        }
        xs4[i] = v;
    }
    __syncthreads();

    const int warp = tid >> 5;
    const int lane = tid & 31;
    const int rbase = warp * 8;

    float4 acc[8];
#pragma unroll
    for (int i = 0; i < 8; i++) acc[i] = make_float4(0.f, 0.f, 0.f, 0.f);

    const float4* W4 = (const float4*)W;
#pragma unroll 4
    for (int k = 0; k < F; k++) {
        float4 wv = W4[k * 32 + lane];
#pragma unroll
        for (int i = 0; i < 8; i++) {
            float xv = xs[(rbase + i) * F + k];
            acc[i].x = fmaf(xv, wv.x, acc[i].x);
            acc[i].y = fmaf(xv, wv.y, acc[i].y);
            acc[i].z = fmaf(xv, wv.z, acc[i].z);
            acc[i].w = fmaf(xv, wv.w, acc[i].w);
        }
    }

#pragma unroll
    for (int i = 0; i < 8; i++) {
        int gr = row0 + rbase + i;
        if (gr < nrows)
            *(float4*)&out[(size_t)gr * F + lane * 4] = acc[i];
    }
}

// ---------------------------------------------------------------------------
// CSR SpMM: warp per row. dst[r,:] = bias + sum_e w_e * src[col_e,:].
// Register accumulation -> single float4 store per lane (no global RED).
// STATS: fuse BN sum/sumsq accumulation (block-reduced, 1 atomic/feature/block).
// ---------------------------------------------------------------------------
template <bool STATS>
__global__ void spmm_csr_kernel(const float* __restrict__ src, float* __restrict__ dst,
                                const float* __restrict__ bias) {
    const int lane = threadIdx.x & 31;
    const int wid = threadIdx.x >> 5;                      // 0..7
    const int gwarp = (blockIdx.x * blockDim.x + threadIdx.x) >> 5;
    const int nwarps = (gridDim.x * blockDim.x) >> 5;

    const float4* src4 = (const float4*)src;
    float4* dst4 = (float4*)dst;
    const float4 bias4 = ((const float4*)bias)[lane];

    float4 ls = make_float4(0.f, 0.f, 0.f, 0.f);   // per-lane feature sums
    float4 lq = make_float4(0.f, 0.f, 0.f, 0.f);   // per-lane feature sumsq

    for (int r = gwarp; r < N_NODES; r += nwarps) {
        const int s = g_row_start[r];
        const int e = g_row_start[r + 1];
        float4 acc = bias4;
        for (int base = s; base < e; base += 32) {
            int n = min(32, e - base);
            int2 m = make_int2(0, 0);
            if (lane < n) m = g_ecw[base + lane];
            for (int j = 0; j < n; j++) {
                int cj = __shfl_sync(0xffffffffu, m.x, j);
                float wj = __int_as_float(__shfl_sync(0xffffffffu, m.y, j));
                float4 v = src4[(size_t)cj * 32 + lane];
                acc.x = fmaf(v.x, wj, acc.x);
                acc.y = fmaf(v.y, wj, acc.y);
                acc.z = fmaf(v.z, wj, acc.z);
                acc.w = fmaf(v.w, wj, acc.w);
            }
        }
        dst4[(size_t)r * 32 + lane] = acc;
        if (STATS) {
            ls.x += acc.x; ls.y += acc.y; ls.z += acc.z; ls.w += acc.w;
            lq.x = fmaf(acc.x, acc.x, lq.x);
            lq.y = fmaf(acc.y, acc.y, lq.y);
            lq.z = fmaf(acc.z, acc.z, lq.z);
            lq.w = fmaf(acc.w, acc.w, lq.w);
        }
    }

    if (STATS) {
        __shared__ float ssum[8 * F];
        __shared__ float ssq[8 * F];
        float4* ssum4 = (float4*)&ssum[wid * F + lane * 4];
        float4* ssq4 = (float4*)&ssq[wid * F + lane * 4];
        *ssum4 = ls;
        *ssq4 = lq;
        __syncthreads();
        int tid = threadIdx.x;
        if (tid < F) {
            float s = 0.f;
#pragma unroll
            for (int w = 0; w < 8; w++) s += ssum[w * F + tid];
            atomicAdd(&g_stats[tid], s);
        } else {
            int f = tid - F;
            float q = 0.f;
#pragma unroll
            for (int w = 0; w < 8; w++) q += ssq[w * F + f];
            atomicAdd(&g_stats[F + f], q);
        }
    }
}

// ---------------------------------------------------------------------------
// Launch: CSR build -> gemm1 -> spmm1(+bias,+stats) -> gemm2(fused BN) -> spmm2(+bias)
// ---------------------------------------------------------------------------
extern "C" void kernel_launch(void* const* d_in, const int* in_sizes, int n_in,
                              void* d_out, int out_size) {
    const float* x     = (const float*)d_in[0];
    const int*   erow  = (const int*)d_in[1];
    const int*   ecol  = (const int*)d_in[2];
    const float* ew    = (const float*)d_in[3];
    const float* W1    = (const float*)d_in[4];
    const float* b1    = (const float*)d_in[5];
    const float* W2    = (const float*)d_in[6];
    const float* b2    = (const float*)d_in[7];
    const float* gamma = (const float*)d_in[8];
    const float* beta  = (const float*)d_in[9];
    float* out = (float*)d_out;
    const int E = in_sizes[1];

    float *ga, *gb;
    cudaGetSymbolAddress((void**)&ga, g_a);
    cudaGetSymbolAddress((void**)&gb, g_b);

    const int gemm_blocks = (N_NODES + 63) / 64;

    // CSR build (amortized over both SpMMs)
    zero_kernel<<<512, 256>>>();
    hist_kernel<<<2048, 256>>>(erow, E);
    scan1_kernel<<<NCHUNKS, CHUNK>>>();
    scan2_kernel<<<1, 128>>>();
    scan3_kernel<<<(N_NODES + 256) / 256, 256>>>(E);
    scatter_kernel<<<2048, 256>>>(erow, ecol, ew, E);

    // t1 = x @ W1
    gemm128_kernel<false><<<gemm_blocks, 256>>>(x, W1, ga, N_NODES, nullptr, nullptr);
    // h1 = A @ t1 + b1, fused BN stats
    spmm_csr_kernel<true><<<2048, 256>>>(ga, gb, b1);
    // h2 = relu(bn(h1)) @ W2
    gemm128_kernel<true><<<gemm_blocks, 256>>>(gb, W2, ga, N_NODES, gamma, beta);
    // out = A @ h2 + b2
    spmm_csr_kernel<false><<<2048, 256>>>(ga, out, b2);
}

// round 6
// speedup vs baseline: 1.3689x; 1.0390x over previous
#include <cuda_runtime.h>
#include <cuda_bf16.h>
#include <mma.h>
#include <cstdint>

using namespace nvcuda;

#define N_NODES 100000
#define N_EDGES_MAX 1600000
#define F 128
#define BN_EPS 1e-5f
#define CHUNK 1024
#define NCHUNKS ((N_NODES + CHUNK - 1) / CHUNK)   // 98
#define M_TILE 128
#define GEMM_BLOCKS ((N_NODES + M_TILE - 1) / M_TILE)  // 782
#define N_PAD (GEMM_BLOCKS * M_TILE)               // 100096 (padded rows for unguarded stores)
#define A_STRIDE 136                               // smem lda (bf16 elems), conflict-free

// ---------------------------------------------------------------------------
// Scratch (__device__ globals; allocation-free rule)
// ---------------------------------------------------------------------------
__device__ float g_a[(size_t)N_PAD * F];       // t1 = x@W1, later h2 (padded)
__device__ float g_b[(size_t)N_PAD * F];       // h1 (padded)
__device__ float g_stats[2 * F];               // [sum, sumsq] per feature
__device__ int   g_count[N_NODES];
__device__ int   g_row_start[N_NODES + 1];     // chunk-local exclusive prefix
__device__ int   g_cursor[N_NODES];
__device__ int   g_chunksum[NCHUNKS];
__device__ int   g_chunkoff[NCHUNKS];
__device__ int2  g_ecw[N_EDGES_MAX];           // row-grouped {col, weight-bits}
// Plain row-major bf16 hi/lo images of W1/W2 ([K=128, N=128])
__device__ __nv_bfloat16 g_w1hi[F * F];
__device__ __nv_bfloat16 g_w1lo[F * F];
__device__ __nv_bfloat16 g_w2hi[F * F];
__device__ __nv_bfloat16 g_w2lo[F * F];

// ---------------------------------------------------------------------------
// Prep: zero counts/stats + split W1/W2 into bf16 hi/lo (row-major)
// ---------------------------------------------------------------------------
__global__ void prep_kernel(const float* __restrict__ W1, const float* __restrict__ W2) {
    int idx = blockIdx.x * blockDim.x + threadIdx.x;
    int stride = gridDim.x * blockDim.x;
    if (idx < 2 * F) g_stats[idx] = 0.0f;
    for (int i = idx; i < N_NODES; i += stride) g_count[i] = 0;

    for (int i = idx; i < 2 * F * F; i += stride) {
        int m = i >> 14;            // 0 -> W1, 1 -> W2
        int e = i & (F * F - 1);
        float w = m ? W2[e] : W1[e];
        __nv_bfloat16 hi = __float2bfloat16_rn(w);
        __nv_bfloat16 lo = __float2bfloat16_rn(w - __bfloat162float(hi));
        if (m) { g_w2hi[e] = hi; g_w2lo[e] = lo; }
        else   { g_w1hi[e] = hi; g_w1lo[e] = lo; }
    }
}

// ---------------------------------------------------------------------------
// CSR build
// ---------------------------------------------------------------------------
__global__ void hist_kernel(const int* __restrict__ rows, int E) {
    int idx = blockIdx.x * blockDim.x + threadIdx.x;
    for (int e = idx; e < E; e += gridDim.x * blockDim.x)
        atomicAdd(&g_count[rows[e]], 1);
}

__global__ void scan1_kernel() {
    __shared__ int sm[CHUNK];
    int tid = threadIdx.x;
    int i = blockIdx.x * CHUNK + tid;
    int val = (i < N_NODES) ? g_count[i] : 0;
    sm[tid] = val;
    __syncthreads();
    for (int off = 1; off < CHUNK; off <<= 1) {
        int t = (tid >= off) ? sm[tid - off] : 0;
        __syncthreads();
        sm[tid] += t;
        __syncthreads();
    }
    int excl = sm[tid] - val;
    if (i < N_NODES + 1) g_row_start[i] = excl;   // chunk-local exclusive
    if (i < N_NODES) g_cursor[i] = excl;
    if (tid == CHUNK - 1) g_chunksum[blockIdx.x] = sm[tid];
}

__global__ void scan2_kernel() {
    __shared__ int sm[128];
    int tid = threadIdx.x;
    int val = (tid < NCHUNKS) ? g_chunksum[tid] : 0;
    sm[tid] = val;
    __syncthreads();
    for (int off = 1; off < 128; off <<= 1) {
        int t = (tid >= off) ? sm[tid - off] : 0;
        __syncthreads();
        sm[tid] += t;
        __syncthreads();
    }
    if (tid < NCHUNKS) g_chunkoff[tid] = sm[tid] - val;
}

__global__ void scatter_kernel(const int* __restrict__ rows, const int* __restrict__ cols,
                               const float* __restrict__ ew, int E) {
    int idx = blockIdx.x * blockDim.x + threadIdx.x;
    for (int e = idx; e < E; e += gridDim.x * blockDim.x) {
        int r = rows[e];
        int pos = atomicAdd(&g_cursor[r], 1) + g_chunkoff[r >> 10];
        g_ecw[pos] = make_int2(cols[e], __float_as_int(ew[e]));
    }
}

// ---------------------------------------------------------------------------
// WMMA bf16 GEMM with 3-term split: out = transform(X) @ W.
// CTA = 128x128 tile, 8 warps in 4x2 grid; warp = 32x64 (2x4 wmma tiles).
// A converted to bf16 hi/lo in smem (padded stride); B frags loaded from
// pre-split global images (L1-resident).  Stores unguarded into padded out.
// ---------------------------------------------------------------------------
#define GEMM_SMEM (2 * 128 * A_STRIDE * 2)   // a_hi + a_lo, bf16

template <bool FUSE_BN>
__global__ void __launch_bounds__(256) gemm_wmma_kernel(
    const float* __restrict__ X,
    const __nv_bfloat16* __restrict__ Whi, const __nv_bfloat16* __restrict__ Wlo,
    float* __restrict__ out, int nrows,
    const float* __restrict__ gamma, const float* __restrict__ beta) {
    extern __shared__ char smem[];
    __nv_bfloat16* a_hi = (__nv_bfloat16*)smem;
    __nv_bfloat16* a_lo = a_hi + 128 * A_STRIDE;
    __shared__ float scale_s[F];
    __shared__ float shift_s[F];

    const int tid = threadIdx.x;

    if (FUSE_BN) {
        if (tid < F) {
            const float inv = 1.0f / (float)N_NODES;
            float mean = g_stats[tid] * inv;
            float var = g_stats[F + tid] * inv - mean * mean;
            float sc = gamma[tid] * rsqrtf(var + BN_EPS);
            scale_s[tid] = sc;
            shift_s[tid] = beta[tid] - mean * sc;
        }
        __syncthreads();
    }

    // Convert X tile -> bf16 hi/lo in smem (guarded loads, zero fill)
    const int row0 = blockIdx.x * M_TILE;
    const float4* X4 = (const float4*)X;
    for (int i = tid; i < 128 * 32; i += 256) {
        int r = i >> 5;
        int c4 = i & 31;
        int gr = row0 + r;
        float4 v = make_float4(0.f, 0.f, 0.f, 0.f);
        if (gr < nrows) v = X4[(size_t)gr * 32 + c4];
        if (FUSE_BN) {
            int f = c4 * 4;
            v.x = fmaxf(fmaf(v.x, scale_s[f + 0], shift_s[f + 0]), 0.f);
            v.y = fmaxf(fmaf(v.y, scale_s[f + 1], shift_s[f + 1]), 0.f);
            v.z = fmaxf(fmaf(v.z, scale_s[f + 2], shift_s[f + 2]), 0.f);
            v.w = fmaxf(fmaf(v.w, scale_s[f + 3], shift_s[f + 3]), 0.f);
        }
        __nv_bfloat16 hx = __float2bfloat16_rn(v.x), hy = __float2bfloat16_rn(v.y);
        __nv_bfloat16 hz = __float2bfloat16_rn(v.z), hw = __float2bfloat16_rn(v.w);
        __nv_bfloat16 lx = __float2bfloat16_rn(v.x - __bfloat162float(hx));
        __nv_bfloat16 ly = __float2bfloat16_rn(v.y - __bfloat162float(hy));
        __nv_bfloat16 lz = __float2bfloat16_rn(v.z - __bfloat162float(hz));
        __nv_bfloat16 lw = __float2bfloat16_rn(v.w - __bfloat162float(hw));
        int base = r * A_STRIDE + c4 * 4;
        uint2 hp, lp;
        hp.x = (uint32_t)__bfloat16_as_ushort(hx) | ((uint32_t)__bfloat16_as_ushort(hy) << 16);
        hp.y = (uint32_t)__bfloat16_as_ushort(hz) | ((uint32_t)__bfloat16_as_ushort(hw) << 16);
        lp.x = (uint32_t)__bfloat16_as_ushort(lx) | ((uint32_t)__bfloat16_as_ushort(ly) << 16);
        lp.y = (uint32_t)__bfloat16_as_ushort(lz) | ((uint32_t)__bfloat16_as_ushort(lw) << 16);
        *(uint2*)&a_hi[base] = hp;
        *(uint2*)&a_lo[base] = lp;
    }
    __syncthreads();

    const int wid = tid >> 5;
    const int wm = wid & 3;        // 0..3: 32-row band
    const int wn = wid >> 2;       // 0..1: 64-col band

    wmma::fragment<wmma::accumulator, 16, 16, 16, float> acc[2][4];
#pragma unroll
    for (int mt = 0; mt < 2; mt++)
#pragma unroll
        for (int nt = 0; nt < 4; nt++)
            wmma::fill_fragment(acc[mt][nt], 0.0f);

    const int mrow0 = wm * 32;
    const int ncol0 = wn * 64;

#pragma unroll
    for (int k0 = 0; k0 < F; k0 += 16) {
        wmma::fragment<wmma::matrix_a, 16, 16, 16, __nv_bfloat16, wmma::row_major> ah[2], al[2];
#pragma unroll
        for (int mt = 0; mt < 2; mt++) {
            wmma::load_matrix_sync(ah[mt], &a_hi[(mrow0 + mt * 16) * A_STRIDE + k0], A_STRIDE);
            wmma::load_matrix_sync(al[mt], &a_lo[(mrow0 + mt * 16) * A_STRIDE + k0], A_STRIDE);
        }
#pragma unroll
        for (int nt = 0; nt < 4; nt++) {
            wmma::fragment<wmma::matrix_b, 16, 16, 16, __nv_bfloat16, wmma::row_major> bh, bl;
            wmma::load_matrix_sync(bh, Whi + k0 * F + ncol0 + nt * 16, F);
            wmma::load_matrix_sync(bl, Wlo + k0 * F + ncol0 + nt * 16, F);
#pragma unroll
            for (int mt = 0; mt < 2; mt++) {
                wmma::mma_sync(acc[mt][nt], ah[mt], bh, acc[mt][nt]);
                wmma::mma_sync(acc[mt][nt], al[mt], bh, acc[mt][nt]);
                wmma::mma_sync(acc[mt][nt], ah[mt], bl, acc[mt][nt]);
            }
        }
    }

    // Store (out is padded to N_PAD rows; no guard needed)
#pragma unroll
    for (int mt = 0; mt < 2; mt++) {
        int gr = row0 + mrow0 + mt * 16;
#pragma unroll
        for (int nt = 0; nt < 4; nt++)
            wmma::store_matrix_sync(&out[(size_t)gr * F + ncol0 + nt * 16],
                                    acc[mt][nt], F, wmma::mem_row_major);
    }
}

// ---------------------------------------------------------------------------
// CSR SpMM: warp per row; register accumulation; optional fused BN stats.
// ---------------------------------------------------------------------------
template <bool STATS>
__global__ void spmm_csr_kernel(const float* __restrict__ src, float* __restrict__ dst,
                                const float* __restrict__ bias) {
    const int lane = threadIdx.x & 31;
    const int wid = threadIdx.x >> 5;
    const int gwarp = (blockIdx.x * blockDim.x + threadIdx.x) >> 5;
    const int nwarps = (gridDim.x * blockDim.x) >> 5;

    const float4* src4 = (const float4*)src;
    float4* dst4 = (float4*)dst;
    const float4 bias4 = ((const float4*)bias)[lane];

    float4 ls = make_float4(0.f, 0.f, 0.f, 0.f);
    float4 lq = make_float4(0.f, 0.f, 0.f, 0.f);

    for (int r = gwarp; r < N_NODES; r += nwarps) {
        const int s = g_row_start[r] + g_chunkoff[r >> 10];
        const int e = g_row_start[r + 1] + g_chunkoff[(r + 1) >> 10];
        float4 acc = bias4;
        for (int base = s; base < e; base += 32) {
            int n = min(32, e - base);
            int2 m = make_int2(0, 0);
            if (lane < n) m = g_ecw[base + lane];
            for (int j = 0; j < n; j++) {
                int cj = __shfl_sync(0xffffffffu, m.x, j);
                float wj = __int_as_float(__shfl_sync(0xffffffffu, m.y, j));
                float4 v = src4[(size_t)cj * 32 + lane];
                acc.x = fmaf(v.x, wj, acc.x);
                acc.y = fmaf(v.y, wj, acc.y);
                acc.z = fmaf(v.z, wj, acc.z);
                acc.w = fmaf(v.w, wj, acc.w);
            }
        }
        dst4[(size_t)r * 32 + lane] = acc;
        if (STATS) {
            ls.x += acc.x; ls.y += acc.y; ls.z += acc.z; ls.w += acc.w;
            lq.x = fmaf(acc.x, acc.x, lq.x);
            lq.y = fmaf(acc.y, acc.y, lq.y);
            lq.z = fmaf(acc.z, acc.z, lq.z);
            lq.w = fmaf(acc.w, acc.w, lq.w);
        }
    }

    if (STATS) {
        __shared__ float ssum[8 * F];
        __shared__ float ssq[8 * F];
        *(float4*)&ssum[wid * F + lane * 4] = ls;
        *(float4*)&ssq[wid * F + lane * 4] = lq;
        __syncthreads();
        int tid = threadIdx.x;
        if (tid < F) {
            float s = 0.f;
#pragma unroll
            for (int w = 0; w < 8; w++) s += ssum[w * F + tid];
            atomicAdd(&g_stats[tid], s);
        } else {
            int f = tid - F;
            float q = 0.f;
#pragma unroll
            for (int w = 0; w < 8; w++) q += ssq[w * F + f];
            atomicAdd(&g_stats[F + f], q);
        }
    }
}

// ---------------------------------------------------------------------------
// Launch
// ---------------------------------------------------------------------------
extern "C" void kernel_launch(void* const* d_in, const int* in_sizes, int n_in,
                              void* d_out, int out_size) {
    const float* x     = (const float*)d_in[0];
    const int*   erow  = (const int*)d_in[1];
    const int*   ecol  = (const int*)d_in[2];
    const float* ew    = (const float*)d_in[3];
    const float* W1    = (const float*)d_in[4];
    const float* b1    = (const float*)d_in[5];
    const float* W2    = (const float*)d_in[6];
    const float* b2    = (const float*)d_in[7];
    const float* gamma = (const float*)d_in[8];
    const float* beta  = (const float*)d_in[9];
    float* out = (float*)d_out;
    const int E = in_sizes[1];

    float *ga, *gb;
    cudaGetSymbolAddress((void**)&ga, g_a);
    cudaGetSymbolAddress((void**)&gb, g_b);
    __nv_bfloat16 *w1h, *w1l, *w2h, *w2l;
    cudaGetSymbolAddress((void**)&w1h, g_w1hi);
    cudaGetSymbolAddress((void**)&w1l, g_w1lo);
    cudaGetSymbolAddress((void**)&w2h, g_w2hi);
    cudaGetSymbolAddress((void**)&w2l, g_w2lo);

    cudaFuncSetAttribute(gemm_wmma_kernel<false>,
                         cudaFuncAttributeMaxDynamicSharedMemorySize, GEMM_SMEM);
    cudaFuncSetAttribute(gemm_wmma_kernel<true>,
                         cudaFuncAttributeMaxDynamicSharedMemorySize, GEMM_SMEM);

    // Prep (zero counts/stats + W bf16 split) + CSR build
    prep_kernel<<<512, 256>>>(W1, W2);
    hist_kernel<<<2048, 256>>>(erow, E);
    scan1_kernel<<<NCHUNKS, CHUNK>>>();
    scan2_kernel<<<1, 128>>>();
    scatter_kernel<<<2048, 256>>>(erow, ecol, ew, E);

    // t1 = x @ W1
    gemm_wmma_kernel<false><<<GEMM_BLOCKS, 256, GEMM_SMEM>>>(x, w1h, w1l, ga, N_NODES,
                                                             nullptr, nullptr);
    // h1 = A @ t1 + b1, fused BN stats
    spmm_csr_kernel<true><<<2048, 256>>>(ga, gb, b1);
    // h2 = relu(bn(h1)) @ W2
    gemm_wmma_kernel<true><<<GEMM_BLOCKS, 256, GEMM_SMEM>>>(gb, w2h, w2l, ga, N_NODES,
                                                            gamma, beta);
    // out = A @ h2 + b2
    spmm_csr_kernel<false><<<2048, 256>>>(ga, out, b2);
}